// round 8
// baseline (speedup 1.0000x reference)
#include <cuda_runtime.h>
#include <cuda_bf16.h>
#include <stdint.h>

#define THREADS 256
#define ITEMS   8
#define CHUNK   (THREADS * ITEMS)   // 2048
#define NWARPS  (THREADS / 32)      // 8

#define MAX_SLOTS 32768             // >= B*P
#define MAX_MASKW (4u * 1024u * 1024u)   // uint16 words >= B*P*THREADS

__device__ uint16_t g_mask[MAX_MASKW];   // per (slot, tid): tb | (s0<<8)
__device__ int      g_tumAgg[MAX_SLOTS];
__device__ int      g_tumBase[MAX_SLOTS];
__device__ float    g_aggx[MAX_SLOTS], g_aggy[MAX_SLOTS], g_aggz[MAX_SLOTS];
__device__ float    g_basex[MAX_SLOTS], g_basey[MAX_SLOTS], g_basez[MAX_SLOTS];

// ======================= K1: pack masks + tumble aggregates ================
__global__ __launch_bounds__(THREADS)
void k1_pack(const int* __restrict__ states, int T, int P)
{
    const int p = blockIdx.x, b = blockIdx.y;
    const int slot = b * P + p;
    const int tid  = threadIdx.x;
    const int lane = tid & 31, wid = tid >> 5;
    const int* srow = states + (size_t)b * T;
    const int t0 = p * CHUNK + tid * ITEMS;

    int s[8] = {1,1,1,1,1,1,1,1};   // pad: state 1 (non-tumble, speed1)
    if (t0 + ITEMS <= T) {
        int4 a = *reinterpret_cast<const int4*>(srow + t0);
        int4 c = *reinterpret_cast<const int4*>(srow + t0 + 4);
        s[0]=a.x; s[1]=a.y; s[2]=a.z; s[3]=a.w;
        s[4]=c.x; s[5]=c.y; s[6]=c.z; s[7]=c.w;
    } else {
        #pragma unroll
        for (int i = 0; i < ITEMS; i++)
            if (t0 + i < T) s[i] = srow[t0 + i];
    }
    unsigned tb = 0, s0 = 0;
    #pragma unroll
    for (int i = 0; i < ITEMS; i++) {
        tb |= (unsigned)(s[i] == 2) << i;
        s0 |= (unsigned)(s[i] == 0) << i;
    }
    g_mask[(size_t)slot * THREADS + tid] = (uint16_t)(tb | (s0 << 8));

    __shared__ int sw[NWARPS];
    const int wt = __reduce_add_sync(0xffffffffu, __popc(tb));
    if (lane == 0) sw[wid] = wt;
    __syncthreads();
    if (tid == 0) {
        int tot = 0;
        #pragma unroll
        for (int j = 0; j < NWARPS; j++) tot += sw[j];
        g_tumAgg[slot] = tot;
    }
}

// ======================= K2: per-row exclusive scan (int) ==================
__global__ void k2_scan_int(int P)
{
    const int b = blockIdx.x, lane = threadIdx.x;
    int carry = 0;
    for (int j0 = 0; j0 < P; j0 += 32) {
        const int j = j0 + lane;
        const int v = (j < P) ? g_tumAgg[b * P + j] : 0;
        int sc = v;
        #pragma unroll
        for (int d = 1; d < 32; d <<= 1) {
            int y = __shfl_up_sync(0xffffffffu, sc, d);
            if (lane >= d) sc += y;
        }
        const int tot = __shfl_sync(0xffffffffu, sc, 31);
        if (j < P) g_tumBase[b * P + j] = carry + sc - v;
        carry += tot;
    }
}

// helper: per-thread kbase + 24 gathers from the mask word
#define GATHER_BODY(slot_, pk_, erow_, g_, smw_)                              \
    const unsigned tb = (pk_) & 0xffu;                                        \
    const int cnt = __popc(tb);                                               \
    int sc = cnt;                                                             \
    _Pragma("unroll")                                                         \
    for (int d = 1; d < 32; d <<= 1) {                                        \
        int y = __shfl_up_sync(0xffffffffu, sc, d);                           \
        if (lane >= d) sc += y;                                               \
    }                                                                         \
    if (lane == 31) smw_[wid] = sc;                                           \
    __syncthreads();                                                          \
    int kbase = g_tumBase[slot_] + (sc - cnt);                                \
    _Pragma("unroll")                                                         \
    for (int j = 0; j < NWARPS; j++) if (j < wid) kbase += smw_[j];           \
    _Pragma("unroll")                                                         \
    for (int i = 0; i < ITEMS; i++) {                                         \
        const int k = kbase + __popc(tb & ((2u << i) - 1u));                  \
        const float* e = (erow_) + (size_t)k * 3;                             \
        g_[3*i+0] = __ldg(e + 0);                                             \
        g_[3*i+1] = __ldg(e + 1);                                             \
        g_[3*i+2] = __ldg(e + 2);                                             \
    }

// ======================= K3: per-partition float3 sums =====================
__global__ __launch_bounds__(THREADS)
void k3_fsum(const float* __restrict__ e0s,
             const float* __restrict__ speed0,
             const float* __restrict__ speed1,
             int T, int P)
{
    const int p = blockIdx.x, b = blockIdx.y;
    const int slot = b * P + p;
    const int tid = threadIdx.x, lane = tid & 31, wid = tid >> 5;
    const float* erow = e0s + (size_t)b * (T + 1) * 3;
    const float sp0 = speed0[b], sp1 = speed1[b];

    __shared__ int   smw[NWARPS];
    __shared__ float sfx[NWARPS], sfy[NWARPS], sfz[NWARPS];

    const uint16_t pk = g_mask[(size_t)slot * THREADS + tid];
    float g[24];
    GATHER_BODY(slot, pk, erow, g, smw)

    const unsigned s0m = pk >> 8;
    float ax = 0.f, ay = 0.f, az = 0.f;
    #pragma unroll
    for (int i = 0; i < ITEMS; i++) {
        const float sp = ((tb >> i) & 1u) ? 0.f : (((s0m >> i) & 1u) ? sp0 : sp1);
        ax = fmaf(g[3*i+0], sp, ax);
        ay = fmaf(g[3*i+1], sp, ay);
        az = fmaf(g[3*i+2], sp, az);
    }
    #pragma unroll
    for (int d = 16; d; d >>= 1) {
        ax += __shfl_down_sync(0xffffffffu, ax, d);
        ay += __shfl_down_sync(0xffffffffu, ay, d);
        az += __shfl_down_sync(0xffffffffu, az, d);
    }
    if (lane == 0) { sfx[wid] = ax; sfy[wid] = ay; sfz[wid] = az; }
    __syncthreads();
    if (tid == 0) {
        float tx = 0.f, ty = 0.f, tz = 0.f;
        #pragma unroll
        for (int j = 0; j < NWARPS; j++) { tx += sfx[j]; ty += sfy[j]; tz += sfz[j]; }
        g_aggx[slot] = tx; g_aggy[slot] = ty; g_aggz[slot] = tz;
    }
}

// ======================= K4: per-row exclusive scan (float3) ===============
__global__ void k4_scan_f(int P)
{
    const int b = blockIdx.x, lane = threadIdx.x;
    float cx = 0.f, cy = 0.f, cz = 0.f;
    for (int j0 = 0; j0 < P; j0 += 32) {
        const int j = j0 + lane;
        const bool v = (j < P);
        float vx = v ? g_aggx[b * P + j] : 0.f;
        float vy = v ? g_aggy[b * P + j] : 0.f;
        float vz = v ? g_aggz[b * P + j] : 0.f;
        float sx = vx, sy = vy, sz = vz;
        #pragma unroll
        for (int d = 1; d < 32; d <<= 1) {
            float tx = __shfl_up_sync(0xffffffffu, sx, d);
            float ty = __shfl_up_sync(0xffffffffu, sy, d);
            float tz = __shfl_up_sync(0xffffffffu, sz, d);
            if (lane >= d) { sx += tx; sy += ty; sz += tz; }
        }
        const float tx = __shfl_sync(0xffffffffu, sx, 31);
        const float ty = __shfl_sync(0xffffffffu, sy, 31);
        const float tz = __shfl_sync(0xffffffffu, sz, 31);
        if (v) {
            g_basex[b * P + j] = cx + sx - vx;
            g_basey[b * P + j] = cy + sy - vy;
            g_basez[b * P + j] = cz + sz - vz;
        }
        cx += tx; cy += ty; cz += tz;
    }
}

// ======================= K5: final output ==================================
__global__ __launch_bounds__(THREADS)
void k5_out(const float* __restrict__ e0s,
            const float* __restrict__ speed0,
            const float* __restrict__ speed1,
            const float* __restrict__ x0,
            float* __restrict__ X,
            int T, int P)
{
    const int p = blockIdx.x, b = blockIdx.y;
    const int slot = b * P + p;
    const int tid = threadIdx.x, lane = tid & 31, wid = tid >> 5;
    const float* erow = e0s + (size_t)b * (T + 1) * 3;
    float* xrow = X + (size_t)b * T * 3;
    const float sp0 = speed0[b], sp1 = speed1[b];
    const float DT = 0.1f;

    __shared__ int   smw[NWARPS];
    __shared__ float sfx[NWARPS], sfy[NWARPS], sfz[NWARPS];

    const uint16_t pk = g_mask[(size_t)slot * THREADS + tid];
    float g[24];
    GATHER_BODY(slot, pk, erow, g, smw)

    const unsigned s0m = pk >> 8;
    float vx[ITEMS], vy[ITEMS], vz[ITEMS];
    float ax = 0.f, ay = 0.f, az = 0.f;
    #pragma unroll
    for (int i = 0; i < ITEMS; i++) {
        const float sp = ((tb >> i) & 1u) ? 0.f : (((s0m >> i) & 1u) ? sp0 : sp1);
        ax = fmaf(g[3*i+0], sp, ax);
        ay = fmaf(g[3*i+1], sp, ay);
        az = fmaf(g[3*i+2], sp, az);
        vx[i] = ax; vy[i] = ay; vz[i] = az;
    }

    // block exclusive float3 prefix
    float sx = ax, sy = ay, sz = az;
    #pragma unroll
    for (int d = 1; d < 32; d <<= 1) {
        float tx = __shfl_up_sync(0xffffffffu, sx, d);
        float ty = __shfl_up_sync(0xffffffffu, sy, d);
        float tz = __shfl_up_sync(0xffffffffu, sz, d);
        if (lane >= d) { sx += tx; sy += ty; sz += tz; }
    }
    if (lane == 31) { sfx[wid] = sx; sfy[wid] = sy; sfz[wid] = sz; }
    __syncthreads();
    float ex = g_basex[slot] + (sx - ax);
    float ey = g_basey[slot] + (sy - ay);
    float ez = g_basez[slot] + (sz - az);
    #pragma unroll
    for (int j = 0; j < NWARPS; j++)
        if (j < wid) { ex += sfx[j]; ey += sfy[j]; ez += sfz[j]; }

    const float bxc = fmaf(DT, ex, x0[3 * b + 0]);
    const float byc = fmaf(DT, ey, x0[3 * b + 1]);
    const float bzc = fmaf(DT, ez, x0[3 * b + 2]);

    const int t0 = p * CHUNK + tid * ITEMS;
    if (t0 + ITEMS <= T) {
        float4* q = reinterpret_cast<float4*>(xrow + (size_t)t0 * 3);
        #pragma unroll
        for (int gg = 0; gg < 6; gg++) {
            float o[4];
            #pragma unroll
            for (int j4 = 0; j4 < 4; j4++) {
                const int f = gg * 4 + j4;
                const int it = f / 3, d = f % 3;
                const float bc = (d == 0) ? bxc : (d == 1) ? byc : bzc;
                const float vc = (d == 0) ? vx[it] : (d == 1) ? vy[it] : vz[it];
                o[j4] = fmaf(DT, vc, bc);
            }
            __stwt(q + gg, make_float4(o[0], o[1], o[2], o[3]));
        }
    } else {
        #pragma unroll
        for (int i = 0; i < ITEMS; i++) {
            if (t0 + i < T) {
                float* o = xrow + (size_t)(t0 + i) * 3;
                o[0] = fmaf(DT, vx[i], bxc);
                o[1] = fmaf(DT, vy[i], byc);
                o[2] = fmaf(DT, vz[i], bzc);
            }
        }
    }
}

extern "C" void kernel_launch(void* const* d_in, const int* in_sizes, int n_in,
                              void* d_out, int out_size)
{
    const int*   states = (const int*)  d_in[0];
    const float* e0s    = (const float*)d_in[1];
    const float* sp0    = (const float*)d_in[2];
    const float* sp1    = (const float*)d_in[3];
    const float* x0     = (const float*)d_in[4];
    float*       X      = (float*)d_out;

    const int B = in_sizes[2];            // speed_0 has B elements
    const int T = in_sizes[0] / B;        // states is (B, T)
    const int P = (T + CHUNK - 1) / CHUNK;

    dim3 grid(P, B);
    k1_pack    <<<grid, THREADS>>>(states, T, P);
    k2_scan_int<<<B, 32>>>(P);
    k3_fsum    <<<grid, THREADS>>>(e0s, sp0, sp1, T, P);
    k4_scan_f  <<<B, 32>>>(P);
    k5_out     <<<grid, THREADS>>>(e0s, sp0, sp1, x0, X, T, P);
}

// round 9
// speedup vs baseline: 1.1155x; 1.1155x over previous
#include <cuda_runtime.h>
#include <cuda_bf16.h>
#include <stdint.h>

#define THREADS 256
#define ITEMS   8
#define CHUNK   (THREADS * ITEMS)   // 2048
#define NWARPS  (THREADS / 32)      // 8
#define BUFROWS 258                 // max k-range per warp-chunk: 256 tumbles + 1 (+pad)
#define BUFF    (BUFROWS * 3)       // floats per warp buffer

__global__ __launch_bounds__(THREADS, 2)
void traj_scan_kernel(const int*   __restrict__ states,
                      const float* __restrict__ e0s,
                      const float* __restrict__ speed0,
                      const float* __restrict__ speed1,
                      const float* __restrict__ x0,
                      float*       __restrict__ X,
                      int T)
{
    __shared__ float  sbuf[NWARPS][BUFF];     // warp-private staged e0 rows
    __shared__ float4 s_tot[2][NWARPS];       // parity-buffered fused-scan totals
    __shared__ int    s_wi[NWARPS];           // prologue int-scan totals

    const int b = blockIdx.x;
    const int*   srow = states + (size_t)b * T;
    const float* erow = e0s    + (size_t)b * (T + 1) * 3;
    float*       xrow = X      + (size_t)b * T * 3;

    const float sp0 = speed0[b];
    const float sp1 = speed1[b];
    const float ox = x0[3 * b + 0];
    const float oy = x0[3 * b + 1];
    const float oz = x0[3 * b + 2];
    const float DT = 0.1f;

    const int tid  = threadIdx.x;
    const int lane = tid & 31;
    const int wid  = tid >> 5;

    // load 8 states at tbase (+tid*8); pad with state 1 (non-tumble)
    #define LOAD_STATES(tbase, A, B)                                          \
        do {                                                                  \
            const int _t0 = (tbase) + tid * ITEMS;                            \
            if (_t0 + ITEMS <= T) {                                           \
                A = *reinterpret_cast<const int4*>(srow + _t0);               \
                B = *reinterpret_cast<const int4*>(srow + _t0 + 4);           \
            } else {                                                          \
                int _tmp[8] = {1,1,1,1,1,1,1,1};                              \
                _Pragma("unroll")                                             \
                for (int _i = 0; _i < ITEMS; _i++)                            \
                    if (_t0 + _i < T) _tmp[_i] = srow[_t0 + _i];              \
                A = make_int4(_tmp[0], _tmp[1], _tmp[2], _tmp[3]);            \
                B = make_int4(_tmp[4], _tmp[5], _tmp[6], _tmp[7]);            \
            }                                                                 \
        } while (0)

    // tb: tumble bits; s0: state==0 bits; zm: zero-velocity bits (tumble|invalid)
    #define COMPUTE_MASKS(A, B, tbase, tb, s0m, zm, run)                      \
        do {                                                                  \
            const int _t0 = (tbase) + tid * ITEMS;                            \
            const int _s[8] = { A.x, A.y, A.z, A.w, B.x, B.y, B.z, B.w };     \
            tb = 0; s0m = 0; zm = 0; run = 0;                                 \
            _Pragma("unroll")                                                 \
            for (int _i = 0; _i < ITEMS; _i++) {                              \
                const unsigned _isT = (_s[_i] == 2);                          \
                const unsigned _inv = (_t0 + _i >= T);                        \
                tb  |= _isT << _i;                                            \
                s0m |= (unsigned)(_s[_i] == 0) << _i;                         \
                zm  |= (_isT | _inv) << _i;                                   \
                run += (int)_isT;                                             \
            }                                                                 \
        } while (0)

    // warp-cooperative coalesced stage of rows [klo, klo+wtot] into sbuf[wid]
    #define STAGE(klo, wtot)                                                  \
        do {                                                                  \
            const int _cnt = ((wtot) + 1) * 3;                                \
            const float* _src = erow + (size_t)(klo) * 3;                     \
            for (int _idx = lane; _idx < _cnt; _idx += 32)                    \
                sbuf[wid][_idx] = __ldg(_src + _idx);                         \
            __syncwarp();                                                     \
        } while (0)

    // ---------------- prologue: chunk 0 int scan + stage -------------------
    int4 na, nb;
    LOAD_STATES(0, na, nb);
    unsigned mtb, ms0, mzm; int run0;
    COMPUTE_MASKS(na, nb, 0, mtb, ms0, mzm, run0);

    int carry_k, koff_cur;
    {
        int sc = run0;
        #pragma unroll
        for (int d = 1; d < 32; d <<= 1) {
            int y = __shfl_up_sync(0xffffffffu, sc, d);
            if (lane >= d) sc += y;
        }
        if (lane == 31) s_wi[wid] = sc;
        __syncthreads();
        int wexcl = 0, tot = 0, wown = 0;
        #pragma unroll
        for (int j = 0; j < NWARPS; j++) {
            const int v = s_wi[j];
            if (j < wid) wexcl += v;
            if (j == wid) wown = v;
            tot += v;
        }
        koff_cur = sc - run0;            // within-warp exclusive
        carry_k  = tot;
        STAGE(wexcl, wown);              // stage chunk 0 (klo = warp excl base)
    }
    if (CHUNK < T) LOAD_STATES(CHUNK, na, nb);   // states for chunk 1

    float carry_x = 0.f, carry_y = 0.f, carry_z = 0.f;
    int parity = 0;

    // ---------------- main loop -------------------------------------------
    for (int base = 0; base < T; base += CHUNK, parity ^= 1) {
        const bool hn = (base + CHUNK) < T;

        unsigned ntb = 0, ns0 = 0, nzm = 0; int nrun = 0;
        if (hn) COMPUTE_MASKS(na, nb, base + CHUNK, ntb, ns0, nzm, nrun);
        if (base + 2 * CHUNK < T) LOAD_STATES(base + 2 * CHUNK, na, nb);

        // ---- consume staged e0 for chunk i from smem ----
        float vx[ITEMS], vy[ITEMS], vz[ITEMS];
        float ax = 0.f, ay = 0.f, az = 0.f;
        const int obase = koff_cur * 3;
        #pragma unroll
        for (int i = 0; i < ITEMS; i++) {
            const int ro = obase + 3 * __popc(mtb & ((2u << i) - 1u));
            const float sp = ((mzm >> i) & 1u) ? 0.f
                           : (((ms0 >> i) & 1u) ? sp0 : sp1);
            ax = fmaf(sbuf[wid][ro + 0], sp, ax);
            ay = fmaf(sbuf[wid][ro + 1], sp, ay);
            az = fmaf(sbuf[wid][ro + 2], sp, az);
            vx[i] = ax; vy[i] = ay; vz[i] = az;
        }

        // ---- fused block scan of (ax, ay, az, run_{i+1}) — ONE barrier ----
        float sx = ax, sy = ay, sz = az, sr = (float)nrun;
        #pragma unroll
        for (int d = 1; d < 32; d <<= 1) {
            const float tx = __shfl_up_sync(0xffffffffu, sx, d);
            const float ty = __shfl_up_sync(0xffffffffu, sy, d);
            const float tz = __shfl_up_sync(0xffffffffu, sz, d);
            const float tr = __shfl_up_sync(0xffffffffu, sr, d);
            if (lane >= d) { sx += tx; sy += ty; sz += tz; sr += tr; }
        }
        if (lane == 31) s_tot[parity][wid] = make_float4(sx, sy, sz, sr);
        __syncthreads();
        float wxe = 0.f, wye = 0.f, wze = 0.f, wre = 0.f;
        float txs = 0.f, tys = 0.f, tzs = 0.f, trs = 0.f;
        float wown = 0.f;
        #pragma unroll
        for (int j = 0; j < NWARPS; j++) {
            const float4 t = s_tot[parity][j];
            if (j < wid)  { wxe += t.x; wye += t.y; wze += t.z; wre += t.w; }
            if (j == wid) wown = t.w;
            txs += t.x; tys += t.y; tzs += t.z; trs += t.w;
        }
        const float ex = carry_x + wxe + (sx - ax);
        const float ey = carry_y + wye + (sy - ay);
        const float ez = carry_z + wze + (sz - az);

        const int klo_n  = carry_k + (int)wre;         // next chunk warp base
        const int wtot_n = (int)wown;                  // next chunk warp total
        const int koff_n = (int)(sr - (float)nrun);    // next within-warp excl
        carry_k += (int)trs;
        carry_x += txs; carry_y += tys; carry_z += tzs;

        // ---- stage chunk i+1 (coalesced; consumed next iteration) ----
        if (hn) STAGE(klo_n, wtot_n);

        // ---- stores for chunk i (streaming, 6x float4) ----
        const int t0 = base + tid * ITEMS;
        const float bxc = fmaf(DT, ex, ox);
        const float byc = fmaf(DT, ey, oy);
        const float bzc = fmaf(DT, ez, oz);
        if (t0 + ITEMS <= T) {
            float4* q = reinterpret_cast<float4*>(xrow + (size_t)t0 * 3);
            #pragma unroll
            for (int gg = 0; gg < 6; gg++) {
                float o[4];
                #pragma unroll
                for (int j4 = 0; j4 < 4; j4++) {
                    const int f  = gg * 4 + j4;
                    const int it = f / 3;
                    const int d  = f % 3;
                    const float bc = (d == 0) ? bxc : (d == 1) ? byc : bzc;
                    const float vc = (d == 0) ? vx[it] : (d == 1) ? vy[it] : vz[it];
                    o[j4] = fmaf(DT, vc, bc);
                }
                __stwt(q + gg, make_float4(o[0], o[1], o[2], o[3]));
            }
        } else {
            #pragma unroll
            for (int i = 0; i < ITEMS; i++) {
                if (t0 + i < T) {
                    float* o = xrow + (size_t)(t0 + i) * 3;
                    o[0] = fmaf(DT, vx[i], bxc);
                    o[1] = fmaf(DT, vy[i], byc);
                    o[2] = fmaf(DT, vz[i], bzc);
                }
            }
        }

        koff_cur = koff_n;
        mtb = ntb; ms0 = ns0; mzm = nzm;
    }

    #undef LOAD_STATES
    #undef COMPUTE_MASKS
    #undef STAGE
}

extern "C" void kernel_launch(void* const* d_in, const int* in_sizes, int n_in,
                              void* d_out, int out_size)
{
    const int*   states = (const int*)  d_in[0];
    const float* e0s    = (const float*)d_in[1];
    const float* sp0    = (const float*)d_in[2];
    const float* sp1    = (const float*)d_in[3];
    const float* x0     = (const float*)d_in[4];
    float*       X      = (float*)d_out;

    const int B = in_sizes[2];           // speed_0 has B elements
    const int T = in_sizes[0] / B;       // states is (B, T)

    traj_scan_kernel<<<B, THREADS>>>(states, e0s, sp0, sp1, x0, X, T);
}

// round 10
// speedup vs baseline: 1.3156x; 1.1794x over previous
#include <cuda_runtime.h>
#include <cuda_bf16.h>
#include <stdint.h>

#define THREADS 256
#define ITEMS   8
#define CHUNK   (THREADS * ITEMS)   // 2048
#define NWARPS  (THREADS / 32)      // 8

__global__ __launch_bounds__(THREADS, 2)
void traj_scan_kernel(const int*   __restrict__ states,
                      const float* __restrict__ e0s,
                      const float* __restrict__ speed0,
                      const float* __restrict__ speed1,
                      const float* __restrict__ x0,
                      float*       __restrict__ X,
                      int T, int P)
{
    __shared__ float s_a[NWARPS][5];
    __shared__ float s_b[NWARPS][4];

    const int b = blockIdx.x;
    const int*   srow = states + (size_t)b * T;
    const float* erow = e0s    + (size_t)b * (T + 1) * 3;
    float*       xrow = X      + (size_t)b * T * 3;

    const float sp0 = speed0[b], sp1 = speed1[b];
    const float ox = x0[3 * b + 0], oy = x0[3 * b + 1], oz = x0[3 * b + 2];
    const float DT = 0.1f;

    const int tid = threadIdx.x, lane = tid & 31, wid = tid >> 5;

    // ---- load 8 states of chunk c (pad state 1 = non-tumble, speed1) ----
    #define LDST(c, A, B) do {                                                \
        const int _t0 = (c) * CHUNK + tid * ITEMS;                            \
        if (_t0 + ITEMS <= T) {                                               \
            A = *reinterpret_cast<const int4*>(srow + _t0);                   \
            B = *reinterpret_cast<const int4*>(srow + _t0 + 4);               \
        } else {                                                              \
            int _s[8] = {1,1,1,1,1,1,1,1};                                    \
            _Pragma("unroll")                                                 \
            for (int _i = 0; _i < ITEMS; _i++)                                \
                if (_t0 + _i < T) _s[_i] = srow[_t0 + _i];                    \
            A = make_int4(_s[0], _s[1], _s[2], _s[3]);                        \
            B = make_int4(_s[4], _s[5], _s[6], _s[7]);                        \
        } } while (0)

    // ---- pack (tb | s0<<8 | zm<<16) into one word ----
    #define MKMASK(A, B, c, M) do {                                           \
        const int _t0 = (c) * CHUNK + tid * ITEMS;                            \
        const int _s[8] = {A.x, A.y, A.z, A.w, B.x, B.y, B.z, B.w};           \
        unsigned _tb = 0, _s0 = 0, _zm = 0;                                   \
        _Pragma("unroll")                                                     \
        for (int _i = 0; _i < ITEMS; _i++) {                                  \
            const unsigned _isT = (_s[_i] == 2);                              \
            const unsigned _inv = (_t0 + _i >= T);                            \
            _tb |= _isT << _i;                                                \
            _s0 |= (unsigned)(_s[_i] == 0) << _i;                             \
            _zm |= (_isT | _inv) << _i;                                       \
        }                                                                     \
        M = _tb | (_s0 << 8) | (_zm << 16); } while (0)

    #define ISSUE(kb, M, g) do {                                              \
        const unsigned _tb = (M) & 0xffu;                                     \
        _Pragma("unroll")                                                     \
        for (int _i = 0; _i < ITEMS; _i++) {                                  \
            const int _k = (kb) + __popc(_tb & ((2u << _i) - 1u));            \
            const float* _e = erow + (size_t)_k * 3;                          \
            g[3*_i+0] = __ldg(_e + 0);                                        \
            g[3*_i+1] = __ldg(_e + 1);                                        \
            g[3*_i+2] = __ldg(_e + 2);                                        \
        } } while (0)

    #define CONSUME(M, g, vx, vy, vz, ax, ay, az) do {                        \
        const unsigned _s0 = ((M) >> 8) & 0xffu, _zm = ((M) >> 16) & 0xffu;   \
        ax = 0.f; ay = 0.f; az = 0.f;                                         \
        _Pragma("unroll")                                                     \
        for (int _i = 0; _i < ITEMS; _i++) {                                  \
            const float _sp = ((_zm >> _i) & 1u) ? 0.f                        \
                            : (((_s0 >> _i) & 1u) ? sp0 : sp1);               \
            ax = fmaf(g[3*_i+0], _sp, ax);                                    \
            ay = fmaf(g[3*_i+1], _sp, ay);                                    \
            az = fmaf(g[3*_i+2], _sp, az);                                    \
            vx[_i] = ax; vy[_i] = ay; vz[_i] = az;                            \
        } } while (0)

    #define STORE_CHUNK(c, vx, vy, vz, ex, ey, ez) do {                       \
        const int _t0 = (c) * CHUNK + tid * ITEMS;                            \
        const float _bx = fmaf(DT, ex, ox);                                   \
        const float _by = fmaf(DT, ey, oy);                                   \
        const float _bz = fmaf(DT, ez, oz);                                   \
        if (_t0 + ITEMS <= T) {                                               \
            float4* _q = reinterpret_cast<float4*>(xrow + (size_t)_t0 * 3);   \
            _Pragma("unroll")                                                 \
            for (int _g = 0; _g < 6; _g++) {                                  \
                float _o[4];                                                  \
                _Pragma("unroll")                                             \
                for (int _j = 0; _j < 4; _j++) {                              \
                    const int _f = _g * 4 + _j, _it = _f / 3, _d = _f % 3;    \
                    const float _bc = (_d==0) ? _bx : (_d==1) ? _by : _bz;    \
                    const float _vc = (_d==0) ? vx[_it]                       \
                                    : (_d==1) ? vy[_it] : vz[_it];            \
                    _o[_j] = fmaf(DT, _vc, _bc);                              \
                }                                                             \
                __stwt(_q + _g, make_float4(_o[0], _o[1], _o[2], _o[3]));     \
            }                                                                 \
        } else {                                                              \
            _Pragma("unroll")                                                 \
            for (int _i = 0; _i < ITEMS; _i++) {                              \
                if (_t0 + _i < T) {                                           \
                    float* _o = xrow + (size_t)(_t0 + _i) * 3;                \
                    _o[0] = fmaf(DT, vx[_i], _bx);                            \
                    _o[1] = fmaf(DT, vy[_i], _by);                            \
                    _o[2] = fmaf(DT, vz[_i], _bz);                            \
                }                                                             \
            }                                                                 \
        } } while (0)

    // ================= prologue: masks 0..3, issue chunks 0,1 ==============
    unsigned m0, m1, m2, m3;
    {
        int4 A, B;
        LDST(0, A, B); MKMASK(A, B, 0, m0);
        LDST(1, A, B); MKMASK(A, B, 1, m1);
        LDST(2, A, B); MKMASK(A, B, 2, m2);
        LDST(3, A, B); MKMASK(A, B, 3, m3);
    }

    float ga[24], gb[24];
    int K;
    {
        const int c0 = __popc(m0 & 0xffu), c1 = __popc(m1 & 0xffu);
        int a0 = c0, a1 = c1;
        #pragma unroll
        for (int d = 1; d < 32; d <<= 1) {
            const int y0 = __shfl_up_sync(0xffffffffu, a0, d);
            const int y1 = __shfl_up_sync(0xffffffffu, a1, d);
            if (lane >= d) { a0 += y0; a1 += y1; }
        }
        if (lane == 31) { s_a[wid][0] = (float)a0; s_a[wid][1] = (float)a1; }
        __syncthreads();
        int w0e = 0, t0s = 0, w1e = 0, t1s = 0;
        #pragma unroll
        for (int j = 0; j < NWARPS; j++) {
            const int v0 = (int)s_a[j][0], v1 = (int)s_a[j][1];
            if (j < wid) { w0e += v0; w1e += v1; }
            t0s += v0; t1s += v1;
        }
        ISSUE(w0e + (a0 - c0), m0, ga);
        if (P > 1) ISSUE(t0s + w1e + (a1 - c1), m1, gb);
        K = t0s + t1s;                     // tumbles through chunk 1
        __syncthreads();                   // protect s_a before body writes
    }

    float cx = 0.f, cy = 0.f, cz = 0.f;

    // ================= main loop: two chunks per body =======================
    for (int i = 0; i < P; i += 2) {
        // early state loads for chunks i+4, i+5 (converted at body bottom)
        int4 pa, pb, qa, qb;
        const bool h4 = (i + 4) < P, h5 = (i + 5) < P;
        if (h4) LDST(i + 4, pa, pb);
        if (h5) LDST(i + 5, qa, qb);

        // ---------- first half: chunk i ----------
        float vx[ITEMS], vy[ITEMS], vz[ITEMS], ax, ay, az;
        CONSUME(m0, ga, vx, vy, vz, ax, ay, az);

        const int c2 = __popc(m2 & 0xffu), c3 = __popc(m3 & 0xffu);
        float sx = ax, sy = ay, sz = az, s2 = (float)c2, s3 = (float)c3;
        #pragma unroll
        for (int d = 1; d < 32; d <<= 1) {
            const float tx = __shfl_up_sync(0xffffffffu, sx, d);
            const float ty = __shfl_up_sync(0xffffffffu, sy, d);
            const float tz = __shfl_up_sync(0xffffffffu, sz, d);
            const float u2 = __shfl_up_sync(0xffffffffu, s2, d);
            const float u3 = __shfl_up_sync(0xffffffffu, s3, d);
            if (lane >= d) { sx += tx; sy += ty; sz += tz; s2 += u2; s3 += u3; }
        }
        if (lane == 31) {
            s_a[wid][0] = sx; s_a[wid][1] = sy; s_a[wid][2] = sz;
            s_a[wid][3] = s2; s_a[wid][4] = s3;
        }
        __syncthreads();
        float wxe = 0.f, wye = 0.f, wze = 0.f, txs = 0.f, tys = 0.f, tzs = 0.f;
        int wre2 = 0, tot2 = 0, wre3 = 0, tot3 = 0;
        #pragma unroll
        for (int j = 0; j < NWARPS; j++) {
            const float fx = s_a[j][0], fy = s_a[j][1], fz = s_a[j][2];
            const int   i2 = (int)s_a[j][3], i3 = (int)s_a[j][4];
            if (j < wid) { wxe += fx; wye += fy; wze += fz; wre2 += i2; wre3 += i3; }
            txs += fx; tys += fy; tzs += fz; tot2 += i2; tot3 += i3;
        }
        const float ex = cx + wxe + (sx - ax);
        const float ey = cy + wye + (sy - ay);
        const float ez = cz + wze + (sz - az);
        const int kb2 = K + wre2 + ((int)s2 - c2);
        const int kb3 = K + tot2 + wre3 + ((int)s3 - c3);
        cx += txs; cy += tys; cz += tzs;
        K += tot2 + tot3;

        if (i + 2 < P) ISSUE(kb2, m2, ga);      // flies ~2 chunk-times
        STORE_CHUNK(i, vx, vy, vz, ex, ey, ez);

        // ---------- second half: chunk i+1 ----------
        if (i + 1 < P) {
            CONSUME(m1, gb, vx, vy, vz, ax, ay, az);
            if (i + 3 < P) ISSUE(kb3, m3, gb);  // gb freed by consume

            float tx2 = ax, ty2 = ay, tz2 = az;
            #pragma unroll
            for (int d = 1; d < 32; d <<= 1) {
                const float ux = __shfl_up_sync(0xffffffffu, tx2, d);
                const float uy = __shfl_up_sync(0xffffffffu, ty2, d);
                const float uz = __shfl_up_sync(0xffffffffu, tz2, d);
                if (lane >= d) { tx2 += ux; ty2 += uy; tz2 += uz; }
            }
            if (lane == 31) {
                s_b[wid][0] = tx2; s_b[wid][1] = ty2; s_b[wid][2] = tz2;
            }
            __syncthreads();
            float wx2 = 0.f, wy2 = 0.f, wz2 = 0.f, tx2s = 0.f, ty2s = 0.f, tz2s = 0.f;
            #pragma unroll
            for (int j = 0; j < NWARPS; j++) {
                const float fx = s_b[j][0], fy = s_b[j][1], fz = s_b[j][2];
                if (j < wid) { wx2 += fx; wy2 += fy; wz2 += fz; }
                tx2s += fx; ty2s += fy; tz2s += fz;
            }
            const float ex2 = cx + wx2 + (tx2 - ax);
            const float ey2 = cy + wy2 + (ty2 - ay);
            const float ez2 = cz + wz2 + (tz2 - az);
            cx += tx2s; cy += ty2s; cz += tz2s;

            STORE_CHUNK(i + 1, vx, vy, vz, ex2, ey2, ez2);
        }

        // rotate masks; convert early-loaded states
        m0 = m2; m1 = m3;
        if (h4) MKMASK(pa, pb, i + 4, m2); else m2 = 0x00FF0000u;
        if (h5) MKMASK(qa, qb, i + 5, m3); else m3 = 0x00FF0000u;
    }

    #undef LDST
    #undef MKMASK
    #undef ISSUE
    #undef CONSUME
    #undef STORE_CHUNK
}

extern "C" void kernel_launch(void* const* d_in, const int* in_sizes, int n_in,
                              void* d_out, int out_size)
{
    const int*   states = (const int*)  d_in[0];
    const float* e0s    = (const float*)d_in[1];
    const float* sp0    = (const float*)d_in[2];
    const float* sp1    = (const float*)d_in[3];
    const float* x0     = (const float*)d_in[4];
    float*       X      = (float*)d_out;

    const int B = in_sizes[2];            // speed_0 has B elements
    const int T = in_sizes[0] / B;        // states is (B, T)
    const int P = (T + CHUNK - 1) / CHUNK;

    traj_scan_kernel<<<B, THREADS>>>(states, e0s, sp0, sp1, x0, X, T, P);
}